// round 1
// baseline (speedup 1.0000x reference)
#include <cuda_runtime.h>
#include <math.h>

// Problem constants
#define E   1024
#define A   64
#define H   16
#define FFD 4096
#define B   2
#define S   2048
#define M   (B*S)        // 4096 rows
#define NQKV (3*E)       // 3072

// ---------------- scratch (device globals; no allocations allowed) ----------
__device__ float g_x[M*E];            // x = emb + pos                (16 MB)
__device__ float g_wqkvT[E*NQKV];     // fused [E, 3E] weight          (12 MB)
__device__ float g_qkv[M*NQKV];       // qkv gemm out / proj tmp       (48 MB)
__device__ float g_q[H*B*S*A];        // Q in [h,b,s,a]                (16 MB)
__device__ float g_attn[M*E];         // concat-head attention out     (16 MB)
__device__ float g_mha[M*E];          // LN(x + attn@Wproj)            (16 MB)
__device__ float g_hidden[M*FFD];     // mha @ W1 + b1                 (64 MB)
__device__ float g_ff[M*E];           // relu(hidden @ W2 + b2)        (16 MB)
__device__ float g_ffout[M*E];        // LN(mha + ff)                  (16 MB)

// ---------------- elementwise add (float4) ----------------------------------
__global__ void k_add(const float4* __restrict__ a, const float4* __restrict__ b,
                      float4* __restrict__ o) {
    int i = blockIdx.x * blockDim.x + threadIdx.x;
    float4 x = a[i], y = b[i];
    x.x += y.x; x.y += y.y; x.z += y.z; x.w += y.w;
    o[i] = x;
}

// ---------------- fuse Wq/Wk/Wv [H,E,A] -> [E, 3E] --------------------------
__global__ void k_wqkv(const float* __restrict__ Wq, const float* __restrict__ Wk,
                       const float* __restrict__ Wv, float* __restrict__ out) {
    int idx = blockIdx.x * blockDim.x + threadIdx.x;   // over 3*H*E*A = 3*E*E
    int qkv = idx / (E*E);
    int rem = idx - qkv * (E*E);                       // [h][e][a]
    int h = rem / (E*A);
    int ea = rem - h * (E*A);
    int e = ea / A;
    int a = ea - e * A;
    const float* W = (qkv == 0) ? Wq : (qkv == 1) ? Wk : Wv;
    out[(size_t)e * NQKV + qkv * E + h * A + a] = W[rem];
}

// ---------------- generic SGEMM 128x128x16, 8x8/thread ----------------------
#define BM 128
#define BN 128
#define BK 16

__global__ __launch_bounds__(256)
void k_gemm(const float* __restrict__ Ag, const float* __restrict__ Bg,
            float* __restrict__ Cg, int Md, int Nd, int Kd,
            const float* __restrict__ bias, const float* __restrict__ resid,
            int do_relu) {
    __shared__ float As[BK][BM];
    __shared__ float Bs[BK][BN + 4];

    int tid = threadIdx.x;
    int tx = tid & 15, ty = tid >> 4;
    const float* Ab = Ag + (size_t)blockIdx.y * BM * Kd;
    const float* Bb = Bg + blockIdx.x * BN;

    float acc[8][8];
#pragma unroll
    for (int i = 0; i < 8; i++)
#pragma unroll
        for (int j = 0; j < 8; j++) acc[i][j] = 0.f;

    for (int k0 = 0; k0 < Kd; k0 += BK) {
#pragma unroll
        for (int i = 0; i < 2; i++) {
            int s = tid + 256 * i;
            // A tile: 128 rows x 16 cols (4 float4 per row)
            int ar = s >> 2, ac4 = s & 3;
            float4 v = *(const float4*)(Ab + (size_t)ar * Kd + k0 + ac4 * 4);
            As[ac4*4+0][ar] = v.x; As[ac4*4+1][ar] = v.y;
            As[ac4*4+2][ar] = v.z; As[ac4*4+3][ar] = v.w;
            // B tile: 16 rows x 128 cols (32 float4 per row)
            int br = s >> 5, bc4 = s & 31;
            float4 w = *(const float4*)(Bb + (size_t)(k0 + br) * Nd + bc4 * 4);
            *(float4*)&Bs[br][bc4 * 4] = w;
        }
        __syncthreads();
#pragma unroll
        for (int k = 0; k < BK; k++) {
            float a_f[8], b_f[8];
            *(float4*)&a_f[0] = *(const float4*)&As[k][ty * 8];
            *(float4*)&a_f[4] = *(const float4*)&As[k][ty * 8 + 4];
            *(float4*)&b_f[0] = *(const float4*)&Bs[k][tx * 8];
            *(float4*)&b_f[4] = *(const float4*)&Bs[k][tx * 8 + 4];
#pragma unroll
            for (int i = 0; i < 8; i++)
#pragma unroll
                for (int j = 0; j < 8; j++)
                    acc[i][j] += a_f[i] * b_f[j];
        }
        __syncthreads();
    }

    int crow0 = blockIdx.y * BM + ty * 8;
    int ccol0 = blockIdx.x * BN + tx * 8;
#pragma unroll
    for (int i = 0; i < 8; i++) {
        int row = crow0 + i;
        float* cp = Cg + (size_t)row * Nd + ccol0;
#pragma unroll
        for (int j = 0; j < 8; j++) {
            float v = acc[i][j];
            if (bias)  v += bias[ccol0 + j];
            if (resid) v += resid[(size_t)row * Nd + ccol0 + j];
            if (do_relu) v = fmaxf(v, 0.f);
            cp[j] = v;
        }
    }
}

// ---------------- scatter fused qkv -> Q scratch, K/V into d_out ------------
__global__ void k_scatter(const float* __restrict__ qkv, float* __restrict__ q,
                          float* __restrict__ kout, float* __restrict__ vout) {
    int idx = blockIdx.x * blockDim.x + threadIdx.x;   // over M*NQKV
    int row = idx / NQKV;
    int col = idx - row * NQKV;
    int which = col / E;
    int cc = col - which * E;
    int h = cc / A;
    int a = cc - h * A;
    int b = row / S;
    int s = row - b * S;
    size_t dst = (((size_t)h * B + b) * S + s) * A + a;
    float v = qkv[(size_t)idx];
    float* d = (which == 0) ? q : (which == 1) ? kout : vout;
    d[dst] = v;
}

// ---------------- flash-style causal attention -------------------------------
// grid: (S/64, H*B), block: 256. Q/K/V layout [h*B+b][s][a], A=64.
#define ALD 68
#define ATTN_SMEM (4 * 64 * ALD * 4)

__global__ __launch_bounds__(256)
void k_attn(const float* __restrict__ Qg, const float* __restrict__ Kg,
            const float* __restrict__ Vg, float* __restrict__ attn_out) {
    extern __shared__ float sm[];
    float* Qs = sm;
    float* Ks = Qs + 64 * ALD;
    float* Vs = Ks + 64 * ALD;
    float* Ps = Vs + 64 * ALD;

    int hb = blockIdx.y;
    int qt = blockIdx.x;
    int h = hb / B, b = hb - h * B;
    int q0 = qt * 64;
    int tid = threadIdx.x;

    // load Q tile [64][64]
    const float4* Q4 = (const float4*)(Qg + ((size_t)hb * S + q0) * A);
#pragma unroll
    for (int i = tid; i < 64 * 16; i += 256) {
        int r = i >> 4, c = i & 15;
        *(float4*)&Qs[r * ALD + c * 4] = Q4[i];
    }

    int r = tid >> 2;
    int g = tid & 3;
    int cbase = g * 16;
    float m_run = -INFINITY, l_run = 0.f;
    float acc[16];
#pragma unroll
    for (int i = 0; i < 16; i++) acc[i] = 0.f;

    int ntiles = qt + 1;
    int qidx = q0 + r;
    const float scale = 0.03125f;   // 1/sqrt(E) = 1/32

    for (int t = 0; t < ntiles; t++) {
        int k0 = t * 64;
        __syncthreads();
        const float4* K4 = (const float4*)(Kg + ((size_t)hb * S + k0) * A);
        const float4* V4 = (const float4*)(Vg + ((size_t)hb * S + k0) * A);
#pragma unroll
        for (int i = tid; i < 64 * 16; i += 256) {
            int rr = i >> 4, cc = i & 15;
            *(float4*)&Ks[rr * ALD + cc * 4] = K4[i];
            *(float4*)&Vs[rr * ALD + cc * 4] = V4[i];
        }
        __syncthreads();

        // scores: s[i] = dot(Q[r], K[cbase+i])
        float sv[16];
#pragma unroll
        for (int i = 0; i < 16; i++) sv[i] = 0.f;
        for (int k = 0; k < 64; k += 4) {
            float4 q4 = *(const float4*)&Qs[r * ALD + k];
#pragma unroll
            for (int i = 0; i < 16; i++) {
                float4 k4 = *(const float4*)&Ks[(cbase + i) * ALD + k];
                sv[i] += q4.x * k4.x + q4.y * k4.y + q4.z * k4.z + q4.w * k4.w;
            }
        }
        float mloc = -INFINITY;
#pragma unroll
        for (int i = 0; i < 16; i++) {
            int kidx = k0 + cbase + i;
            sv[i] = (kidx <= qidx) ? sv[i] * scale : -INFINITY;
            mloc = fmaxf(mloc, sv[i]);
        }
        mloc = fmaxf(mloc, __shfl_xor_sync(0xffffffff, mloc, 1));
        mloc = fmaxf(mloc, __shfl_xor_sync(0xffffffff, mloc, 2));
        float m_new = fmaxf(m_run, mloc);
        float alpha = __expf(m_run - m_new);

        float lloc = 0.f;
        float p[16];
#pragma unroll
        for (int i = 0; i < 16; i++) { p[i] = __expf(sv[i] - m_new); lloc += p[i]; }
        lloc += __shfl_xor_sync(0xffffffff, lloc, 1);
        lloc += __shfl_xor_sync(0xffffffff, lloc, 2);
        l_run = l_run * alpha + lloc;
        m_run = m_new;
#pragma unroll
        for (int i = 0; i < 16; i++) acc[i] *= alpha;
#pragma unroll
        for (int i = 0; i < 16; i++) Ps[r * ALD + cbase + i] = p[i];
        __syncthreads();

        // acc[d] += sum_c Ps[r][c] * Vs[c][cbase+d]
        for (int c = 0; c < 64; c++) {
            float pv = Ps[r * ALD + c];
            const float* vrow = &Vs[c * ALD + cbase];
            float4 v0 = *(const float4*)(vrow + 0);
            float4 v1 = *(const float4*)(vrow + 4);
            float4 v2 = *(const float4*)(vrow + 8);
            float4 v3 = *(const float4*)(vrow + 12);
            acc[0]  += pv * v0.x; acc[1]  += pv * v0.y; acc[2]  += pv * v0.z; acc[3]  += pv * v0.w;
            acc[4]  += pv * v1.x; acc[5]  += pv * v1.y; acc[6]  += pv * v1.z; acc[7]  += pv * v1.w;
            acc[8]  += pv * v2.x; acc[9]  += pv * v2.y; acc[10] += pv * v2.z; acc[11] += pv * v2.w;
            acc[12] += pv * v3.x; acc[13] += pv * v3.y; acc[14] += pv * v3.z; acc[15] += pv * v3.w;
        }
    }

    float inv_l = 1.f / l_run;
    int row = b * S + q0 + r;
    float* op = attn_out + (size_t)row * E + h * A + cbase;
#pragma unroll
    for (int i = 0; i < 16; i += 4) {
        float4 o4;
        o4.x = acc[i+0] * inv_l; o4.y = acc[i+1] * inv_l;
        o4.z = acc[i+2] * inv_l; o4.w = acc[i+3] * inv_l;
        *(float4*)(op + i) = o4;
    }
}

// ---------------- LayerNorm over rows of 1024 (o = LN(a [+ b])) --------------
__global__ __launch_bounds__(256)
void k_ln(const float* __restrict__ a, const float* __restrict__ b,
          const float* __restrict__ gg, const float* __restrict__ bb,
          float* __restrict__ o) {
    __shared__ float red[16];
    __shared__ float s_mu, s_rstd;
    int row = blockIdx.x;
    int t = threadIdx.x;
    float4 x = ((const float4*)(a + (size_t)row * E))[t];
    if (b) {
        float4 y = ((const float4*)(b + (size_t)row * E))[t];
        x.x += y.x; x.y += y.y; x.z += y.z; x.w += y.w;
    }
    float sum = x.x + x.y + x.z + x.w;
    float sq  = x.x*x.x + x.y*x.y + x.z*x.z + x.w*x.w;
#pragma unroll
    for (int off = 16; off; off >>= 1) {
        sum += __shfl_xor_sync(0xffffffff, sum, off);
        sq  += __shfl_xor_sync(0xffffffff, sq,  off);
    }
    if ((t & 31) == 0) { red[t >> 5] = sum; red[8 + (t >> 5)] = sq; }
    __syncthreads();
    if (t == 0) {
        float ts = 0.f, tq = 0.f;
#pragma unroll
        for (int i = 0; i < 8; i++) { ts += red[i]; tq += red[8 + i]; }
        float mu = ts * (1.f / E);
        float var = tq * (1.f / E) - mu * mu;
        s_mu = mu; s_rstd = rsqrtf(var + 1e-5f);
    }
    __syncthreads();
    float mu = s_mu, rstd = s_rstd;
    float4 g4 = ((const float4*)gg)[t];
    float4 b4 = ((const float4*)bb)[t];
    float4 rr;
    rr.x = (x.x - mu) * rstd * g4.x + b4.x;
    rr.y = (x.y - mu) * rstd * g4.y + b4.y;
    rr.z = (x.z - mu) * rstd * g4.z + b4.z;
    rr.w = (x.w - mu) * rstd * g4.w + b4.w;
    ((float4*)(o + (size_t)row * E))[t] = rr;
}

// ---------------- launch ------------------------------------------------------
extern "C" void kernel_launch(void* const* d_in, const int* in_sizes, int n_in,
                              void* d_out, int out_size) {
    const float* emb    = (const float*)d_in[0];
    const float* pos    = (const float*)d_in[1];
    const float* Wq     = (const float*)d_in[2];
    const float* Wk     = (const float*)d_in[3];
    const float* Wv     = (const float*)d_in[4];
    const float* Wproj  = (const float*)d_in[5];
    const float* W1     = (const float*)d_in[6];
    const float* b1     = (const float*)d_in[7];
    const float* W2     = (const float*)d_in[8];
    const float* b2     = (const float*)d_in[9];
    const float* gattn  = (const float*)d_in[10];
    const float* beattn = (const float*)d_in[11];
    const float* gffn   = (const float*)d_in[12];
    const float* beffn  = (const float*)d_in[13];
    const float* gout   = (const float*)d_in[14];
    const float* beout  = (const float*)d_in[15];

    float* out  = (float*)d_out;
    float* Kout = out + (size_t)M * E;       // K: [H,B,S,A]
    float* Vout = out + (size_t)2 * M * E;   // V: [H,B,S,A]

    float *px, *pwT, *pqkv, *pq, *pattn, *pmha, *phid, *pff, *pffout;
    cudaGetSymbolAddress((void**)&px,    g_x);
    cudaGetSymbolAddress((void**)&pwT,   g_wqkvT);
    cudaGetSymbolAddress((void**)&pqkv,  g_qkv);
    cudaGetSymbolAddress((void**)&pq,    g_q);
    cudaGetSymbolAddress((void**)&pattn, g_attn);
    cudaGetSymbolAddress((void**)&pmha,  g_mha);
    cudaGetSymbolAddress((void**)&phid,  g_hidden);
    cudaGetSymbolAddress((void**)&pff,   g_ff);
    cudaGetSymbolAddress((void**)&pffout,g_ffout);

    cudaFuncSetAttribute(k_attn, cudaFuncAttributeMaxDynamicSharedMemorySize,
                         ATTN_SMEM);

    // x = emb + pos
    k_add<<<(M * E / 4) / 256, 256>>>((const float4*)emb, (const float4*)pos,
                                      (float4*)px);
    // fuse qkv weights
    k_wqkv<<<(3 * E * E) / 256, 256>>>(Wq, Wk, Wv, pwT);
    // qkv = x @ WqkvT   [4096, 3072]
    {
        dim3 grid(NQKV / BN, M / BM);
        k_gemm<<<grid, 256>>>(px, pwT, pqkv, M, NQKV, E, nullptr, nullptr, 0);
    }
    // scatter to Q scratch + K/V outputs
    k_scatter<<<(M * NQKV) / 256, 256>>>(pqkv, pq, Kout, Vout);
    // attention
    {
        dim3 grid(S / 64, H * B);
        k_attn<<<grid, 256, ATTN_SMEM>>>(pq, Kout, Vout, pattn);
    }
    // proj + residual x (into pqkv scratch), then LN -> mha
    {
        dim3 grid(E / BN, M / BM);
        k_gemm<<<grid, 256>>>(pattn, Wproj, pqkv, M, E, E, nullptr, px, 0);
    }
    k_ln<<<M, 256>>>(pqkv, nullptr, gattn, beattn, pmha);
    // hidden = mha @ W1 + b1
    {
        dim3 grid(FFD / BN, M / BM);
        k_gemm<<<grid, 256>>>(pmha, W1, phid, M, FFD, E, b1, nullptr, 0);
    }
    // ff = relu(hidden @ W2 + b2)
    {
        dim3 grid(E / BN, M / BM);
        k_gemm<<<grid, 256>>>(phid, W2, pff, M, E, FFD, b2, nullptr, 1);
    }
    // ff_out = LN(mha + ff); encoded = LN(mha + ff_out) -> d_out
    k_ln<<<M, 256>>>(pmha, pff, gffn, beffn, pffout);
    k_ln<<<M, 256>>>(pmha, pffout, gout, beout, out);
}